// round 5
// baseline (speedup 1.0000x reference)
#include <cuda_runtime.h>
#include <math.h>

#define SUB1 15
#define T_MAX 120000

// ---------------- scratch (device globals — no allocs allowed) ----------------
__device__ float g_syn_e[T_MAX * 16];   // matmul output, channel-padded to 16
__device__ float g_syn_i[T_MAX * 16];
__device__ float g_ke[SUB1 * 104];      // causal kernels, zero-padded 100->104
__device__ float g_ki[SUB1 * 104];
__device__ float g_kh[SUB1 * 104];
__device__ float g_ko[SUB1 * 208];      // acausal obs kernel, zero-padded 201->208

// ---------------- basis functions (fp64, matches numpy) ----------------
__device__ __forceinline__ double cos_basis_val(int b, int d) {
    const double PI_D = 3.141592653589793;
    double raw = 5.0 * log((double)d + 1.0 + 1e-8);
    double phi = 1.5707963267948966 * (double)b;
    if (raw < phi - PI_D || raw > phi + PI_D) return 0.0;
    return 0.5 * cos(raw - phi) + 0.5;
}

__device__ __forceinline__ double obs_basis_val(int b, int x) {
    const double PI_D = 3.141592653589793;
    double phi;
    if (b == 0) {
        phi = 0.0;
    } else if (b & 1) {           // positive-side basis, rows 2i-1 (x >= 0)
        if (x < 0) return 0.0;
        phi = 1.5707963267948966 * (double)((b + 1) >> 1);
    } else {                      // negative-side basis, rows 2i (x <= 0)
        if (x > 0) return 0.0;
        phi = 1.5707963267948966 * (double)(b >> 1);
    }
    double r = 5.0 * log(fabs((double)x) + 1.0 + 1e-8);
    if (r < phi - PI_D || r > phi + PI_D) return 0.0;
    return 0.5 * cos(r - phi) + 0.5;
}

// ---------------- kernel precompute (tiny, runs once per call) ----------------
__global__ void prep_kernel(const float* __restrict__ W_syn,
                            const float* __restrict__ W_hist,
                            const float* __restrict__ W_obs) {
    int idx = blockIdx.x * blockDim.x + threadIdx.x;
    if (idx < SUB1 * 104) {
        int s = idx / 104, d = idx % 104;
        float ke = 0.f, ki = 0.f, kh = 0.f;
        if (d < 100) {
            for (int b = 0; b < 13; b++) {
                float bf = (float)cos_basis_val(b, d);
                ke = fmaf(W_syn[(s * 13 + b) * 2 + 0], bf, ke);
                ki = fmaf(W_syn[(s * 13 + b) * 2 + 1], bf, ki);
                kh = fmaf(W_hist[s * 13 + b], bf, kh);
            }
        }
        g_ke[idx] = ke; g_ki[idx] = ki; g_kh[idx] = kh;
    }
    if (idx < SUB1 * 208) {
        int s = idx / 208, j = idx % 208;
        float ko = 0.f;
        if (j < 201) {
            int x = j - 100;
            for (int b = 0; b < 25; b++)
                ko = fmaf(W_obs[s * 25 + b], (float)obs_basis_val(b, x), ko);
        }
        g_ko[idx] = ko;
    }
}

// ---------------- matmul: syn[t,s] = sum_k S[t,k] * C[s+1,k] ----------------
// 256 threads, 512 rows/block, 2 rows per thread packed into f32x2 accumulators.
// Weights duplicated {w,w} in smem so the inner loop is LDS.64 + FFMA2 only.
template <int K>
__global__ __launch_bounds__(256) void matmul_kernel(const float* __restrict__ S,
                                                     const float* __restrict__ C,
                                                     float* __restrict__ out, int T) {
    extern __shared__ char smraw[];
    float2* Cd = (float2*)smraw;                                   // [SUB1*K] duplicated weights
    float* tile = (float*)(smraw + SUB1 * K * sizeof(float2));     // [8][520] transposed S tile
    const int tid = threadIdx.x;

    for (int i = tid; i < SUB1 * K; i += 256) {
        float w = C[K + i];   // row (s+1) of C_syn: (s+1)*K + k == K + (s*K+k)
        Cd[i] = make_float2(w, w);
    }
    __syncthreads();

    unsigned long long acc[SUB1];
#pragma unroll
    for (int s = 0; s < SUB1; s++) acc[s] = 0ull;

    const int row0 = blockIdx.x * 512;
    for (int k0 = 0; k0 < K; k0 += 8) {
        // cooperative transposed load of a 512x8 S tile
#pragma unroll
        for (int it = 0; it < 4; it++) {
            int li = it * 256 + tid;
            int r = li >> 1, cq = li & 1;
            int row = row0 + r;
            float4 v = make_float4(0.f, 0.f, 0.f, 0.f);
            if (row < T) v = *(const float4*)(S + (size_t)row * K + (k0 + cq * 4));
            tile[(cq * 4 + 0) * 520 + r] = v.x;
            tile[(cq * 4 + 1) * 520 + r] = v.y;
            tile[(cq * 4 + 2) * 520 + r] = v.z;
            tile[(cq * 4 + 3) * 520 + r] = v.w;
        }
        __syncthreads();
#pragma unroll
        for (int c = 0; c < 8; c++) {
            unsigned long long x2 = *(const unsigned long long*)(tile + c * 520 + 2 * tid);
            const float2* wp = Cd + (k0 + c);
#pragma unroll
            for (int s = 0; s < SUB1; s++) {
                unsigned long long w2 = *(const unsigned long long*)(wp + (size_t)s * K);
                asm("fma.rn.f32x2 %0, %1, %2, %0;" : "+l"(acc[s]) : "l"(x2), "l"(w2));
            }
        }
        __syncthreads();
    }

    int ra = row0 + 2 * tid;
#pragma unroll
    for (int s = 0; s < SUB1; s++) {
        float lo, hi;
        asm("mov.b64 {%0, %1}, %2;" : "=f"(lo), "=f"(hi) : "l"(acc[s]));
        if (ra < T)     out[(size_t)ra * 16 + s] = lo;
        if (ra + 1 < T) out[(size_t)(ra + 1) * 16 + s] = hi;
    }
}

// ---------------- sliding-window depthwise conv ----------------
// Thread owns one sub-channel and 8 consecutive t. Circular 8-reg signal window,
// rotation via unroll-by-8 (no register moves). 2 LDS + 8 FMA per tap.
// Computes acc[r] += sum_{d=0}^{NT-1} sig[(base+r-d)*PITCH] * w[d].
template <int NT, int PITCH>
__device__ __forceinline__ void conv_slide(float acc[8], const float* __restrict__ sig,
                                           const float* __restrict__ w, int base) {
    float y[8];
#pragma unroll
    for (int j = 0; j < 8; j++) y[j] = sig[(base + j) * PITCH];
#pragma unroll 1
    for (int d0 = 0; d0 < NT; d0 += 8) {
#pragma unroll
        for (int dd = 0; dd < 8; dd++) {
            float wv = w[d0 + dd];
#pragma unroll
            for (int r = 0; r < 8; r++)
                acc[r] = fmaf(y[(r - dd) & 7], wv, acc[r]);
            y[(7 - dd) & 7] = sig[(base - (d0 + dd) - 1) * PITCH];  // prefetch next tap
        }
    }
}

// out[t,s] = exp( conv_e + conv_i + conv_hist + conv_obs + Theta[s] )
// block: 128 t-steps, 256 threads -> (s = tid&15, t-run = tid>>4, 8 t each)
__global__ __launch_bounds__(256) void conv_kernel(const float* __restrict__ Z_obs,
                                                   const float* __restrict__ Z_hid,
                                                   const float* __restrict__ Theta,
                                                   float* __restrict__ out0,
                                                   float* __restrict__ out1,
                                                   int T) {
    extern __shared__ float sm[];
    float* se = sm;                     // [232][17], origin t0-104
    float* si = se + 232 * 17;          // [232][17], origin t0-104
    float* sh = si + 232 * 17;          // [232][17], origin t0-105 (strictly-past hist)
    float* zo = sh + 232 * 17;          // [336],     origin t0-108
    float* we = zo + 336;               // [15][105]
    float* wi = we + SUB1 * 105;
    float* wh = wi + SUB1 * 105;
    float* wo = wh + SUB1 * 105;        // [15][209]
    const int tid = threadIdx.x;
    const int t0 = blockIdx.x * 128;

    for (int li = tid; li < 232 * 16; li += 256) {
        int lt = li >> 4, s = li & 15;
        int t = t0 - 104 + lt;
        float ve = 0.f, vi2 = 0.f;
        if (t >= 0 && t < T) { ve = g_syn_e[t * 16 + s]; vi2 = g_syn_i[t * 16 + s]; }
        se[lt * 17 + s] = ve;
        si[lt * 17 + s] = vi2;
    }
    for (int li = tid; li < 232 * 15; li += 256) {
        int lt = li / 15, s = li % 15;
        int t = t0 - 105 + lt;
        sh[lt * 17 + s] = (t >= 0 && t < T) ? Z_hid[(size_t)t * SUB1 + s] : 0.f;
    }
    for (int li = tid; li < 336; li += 256) {
        int t = t0 - 108 + li;
        zo[li] = (t >= 0 && t < T) ? Z_obs[t] : 0.f;
    }
    for (int li = tid; li < SUB1 * 104; li += 256) {
        int s = li / 104, d = li % 104;
        we[s * 105 + d] = g_ke[li];
        wi[s * 105 + d] = g_ki[li];
        wh[s * 105 + d] = g_kh[li];
    }
    for (int li = tid; li < SUB1 * 208; li += 256) {
        int s = li / 208, j = li % 208;
        wo[s * 209 + j] = g_ko[li];
    }
    __syncthreads();

    const int s = tid & 15;
    const int trun = tid >> 4;
    if (s >= SUB1) return;   // 16 idle lanes; no barriers after this point

    float acc[8];
    float th = __ldg(Theta + s);
#pragma unroll
    for (int r = 0; r < 8; r++) acc[r] = th;

    const int base = 104 + trun * 8;
    conv_slide<104, 17>(acc, se + s, we + s * 105, base);       // sum_d syn_e[t-d]   * ke[d]
    conv_slide<104, 17>(acc, si + s, wi + s * 105, base);       // sum_d syn_i[t-d]   * ki[d]
    conv_slide<104, 17>(acc, sh + s, wh + s * 105, base);       // sum_d Z_hid[t-1-d] * kh[d]
    conv_slide<208, 1>(acc, zo, wo + s * 209, 208 + trun * 8);  // sum_j Z_obs[t+100-j]*ko[j]

    const int tb = t0 + trun * 8;
#pragma unroll
    for (int r = 0; r < 8; r++) {
        int t = tb + r;
        if (t < T) {
            float v = expf(acc[r]);
            out0[(size_t)t * SUB1 + s] = v;
            out1[(size_t)t * SUB1 + s] = v;
        }
    }
}

extern "C" void kernel_launch(void* const* d_in, const int* in_sizes, int n_in,
                              void* d_out, int out_size) {
    const float* S_e    = (const float*)d_in[0];
    const float* S_i    = (const float*)d_in[1];
    const float* Z_obs  = (const float*)d_in[2];
    const float* Z_hid  = (const float*)d_in[3];
    const float* C_e    = (const float*)d_in[4];
    const float* C_i    = (const float*)d_in[5];
    const float* W_syn  = (const float*)d_in[6];
    const float* W_hist = (const float*)d_in[7];
    const float* W_obs  = (const float*)d_in[8];
    const float* Theta  = (const float*)d_in[9];
    const int T = in_sizes[2];          // Z_obs element count

    float* out0 = (float*)d_out;
    float* out1 = (out_size >= 2 * T * SUB1) ? out0 + (size_t)T * SUB1 : out0;

    const int smem_mm_e = SUB1 * 800 * (int)sizeof(float2) + 8 * 520 * (int)sizeof(float); // 112640
    const int smem_mm_i = SUB1 * 200 * (int)sizeof(float2) + 8 * 520 * (int)sizeof(float); //  40640
    const int smem_conv = (3 * 232 * 17 + 336 + 3 * SUB1 * 105 + SUB1 * 209) * (int)sizeof(float); // 80112

    cudaFuncSetAttribute(matmul_kernel<800>, cudaFuncAttributeMaxDynamicSharedMemorySize, smem_mm_e);
    cudaFuncSetAttribute(matmul_kernel<200>, cudaFuncAttributeMaxDynamicSharedMemorySize, smem_mm_i);
    cudaFuncSetAttribute(conv_kernel,        cudaFuncAttributeMaxDynamicSharedMemorySize, smem_conv);

    float* syn_e_ptr; float* syn_i_ptr;
    cudaGetSymbolAddress((void**)&syn_e_ptr, g_syn_e);
    cudaGetSymbolAddress((void**)&syn_i_ptr, g_syn_i);

    prep_kernel<<<(SUB1 * 208 + 255) / 256, 256>>>(W_syn, W_hist, W_obs);

    int mm_blocks = (T + 511) / 512;
    matmul_kernel<800><<<mm_blocks, 256, smem_mm_e>>>(S_e, C_e, syn_e_ptr, T);
    matmul_kernel<200><<<mm_blocks, 256, smem_mm_i>>>(S_i, C_i, syn_i_ptr, T);

    int conv_blocks = (T + 127) / 128;
    conv_kernel<<<conv_blocks, 256, smem_conv>>>(Z_obs, Z_hid, Theta, out0, out1, T);
}

// round 6
// speedup vs baseline: 1.4189x; 1.4189x over previous
#include <cuda_runtime.h>
#include <math.h>

#define SUB1 15
#define T_MAX 120000

// ---------------- scratch (device globals — no allocs allowed) ----------------
__device__ float  g_syn[T_MAX * 32];      // interleaved {e,i} per (t,s): [t][s][2], s-pitch 32
__device__ float2 g_wei[SUB1 * 105];      // {ke[d], ki[d]}
__device__ float2 g_whz[SUB1 * 105];      // {kh[d], ko[d]}        (obs taps 0..103)
__device__ float  g_kohi[SUB1 * 105];     // ko[104+d]             (obs taps 104..207)

// ---------------- basis functions (fp64, matches numpy) ----------------
__device__ __forceinline__ double cos_basis_val(int b, int d) {
    const double PI_D = 3.141592653589793;
    double raw = 5.0 * log((double)d + 1.0 + 1e-8);
    double phi = 1.5707963267948966 * (double)b;
    if (raw < phi - PI_D || raw > phi + PI_D) return 0.0;
    return 0.5 * cos(raw - phi) + 0.5;
}

__device__ __forceinline__ double obs_basis_val(int b, int x) {
    const double PI_D = 3.141592653589793;
    double phi;
    if (b == 0) {
        phi = 0.0;
    } else if (b & 1) {           // positive-side basis (x >= 0)
        if (x < 0) return 0.0;
        phi = 1.5707963267948966 * (double)((b + 1) >> 1);
    } else {                      // negative-side basis (x <= 0)
        if (x > 0) return 0.0;
        phi = 1.5707963267948966 * (double)(b >> 1);
    }
    double r = 5.0 * log(fabs((double)x) + 1.0 + 1e-8);
    if (r < phi - PI_D || r > phi + PI_D) return 0.0;
    return 0.5 * cos(r - phi) + 0.5;
}

// ---------------- kernel precompute (tiny, runs once per call) ----------------
__global__ void prep_kernel(const float* __restrict__ W_syn,
                            const float* __restrict__ W_hist,
                            const float* __restrict__ W_obs) {
    int idx = blockIdx.x * blockDim.x + threadIdx.x;
    if (idx >= SUB1 * 105) return;
    int s = idx / 105, d = idx % 105;
    float ke = 0.f, ki = 0.f, kh = 0.f, ko = 0.f, ko2 = 0.f;
    if (d < 100) {
        for (int b = 0; b < 13; b++) {
            float bf = (float)cos_basis_val(b, d);
            ke = fmaf(W_syn[(s * 13 + b) * 2 + 0], bf, ke);
            ki = fmaf(W_syn[(s * 13 + b) * 2 + 1], bf, ki);
            kh = fmaf(W_hist[s * 13 + b], bf, kh);
        }
    }
    if (d < 104) {  // obs tap j = d, x = j - 100
        for (int b = 0; b < 25; b++)
            ko = fmaf(W_obs[s * 25 + b], (float)obs_basis_val(b, d - 100), ko);
    }
    if (d <= 96) {  // obs tap j = 104 + d, x = d + 4  (j <= 200)
        for (int b = 0; b < 25; b++)
            ko2 = fmaf(W_obs[s * 25 + b], (float)obs_basis_val(b, d + 4), ko2);
    }
    g_wei[idx]  = make_float2(ke, ki);
    g_whz[idx]  = make_float2(kh, ko);
    g_kohi[idx] = ko2;
}

// ---------------- matmul: syn[t,s] = sum_k S[t,k] * C[s+1,k] ----------------
// k-pair packing into f32x2. 256 threads, 2 rows/thread (tid, tid+256), 512 rows/block.
// Weights streamed per KC-column chunk into a tiny smem buffer (natural float2, no dup).
// Inner loop per k-pair: 2 LDS.64 (x) + 15 LDS.64 (broadcast w) + 30 FFMA2.
template <int K, int KC>
__global__ __launch_bounds__(256, 2) void matmul_kernel(const float* __restrict__ S,
                                                        const float* __restrict__ C,
                                                        float* __restrict__ out,
                                                        int T, int ch) {
    extern __shared__ float sm[];
    const int PITCH = KC + 2;                    // even -> float2-aligned rows; odd mod 32 banks
    float* tile = sm;                            // [512][PITCH]
    float2* wbuf = (float2*)(sm + 512 * PITCH);  // [15][KC/2]
    const int tid = threadIdx.x;
    const int row_base = blockIdx.x * 512;

    unsigned long long acc[2 * SUB1];
#pragma unroll
    for (int i = 0; i < 2 * SUB1; i++) acc[i] = 0ull;

    for (int k0 = 0; k0 < K; k0 += KC) {
        // weight chunk: rows 1..15 of C, cols k0..k0+KC-1
        for (int li = tid; li < SUB1 * (KC / 2); li += 256) {
            int s = li / (KC / 2), q = li % (KC / 2);
            wbuf[li] = *(const float2*)(C + (size_t)(s + 1) * K + k0 + 2 * q);
        }
        // x tile: 512 rows x KC cols, coalesced float4 loads
#pragma unroll
        for (int it = 0; it < (512 * KC / 4) / 256; it++) {
            int li = it * 256 + tid;
            int r = li / (KC / 4), q = li % (KC / 4);
            int row = row_base + r;
            float4 v = make_float4(0.f, 0.f, 0.f, 0.f);
            if (row < T) v = *(const float4*)(S + (size_t)row * K + k0 + 4 * q);
            float* dst = tile + r * PITCH + 4 * q;
            *(float2*)(dst)     = make_float2(v.x, v.y);
            *(float2*)(dst + 2) = make_float2(v.z, v.w);
        }
        __syncthreads();
#pragma unroll
        for (int j = 0; j < KC / 2; j++) {
            unsigned long long x0 = *(const unsigned long long*)(tile + tid * PITCH + 2 * j);
            unsigned long long x1 = *(const unsigned long long*)(tile + (tid + 256) * PITCH + 2 * j);
#pragma unroll
            for (int s = 0; s < SUB1; s++) {
                unsigned long long w2 = *(const unsigned long long*)(wbuf + s * (KC / 2) + j);
                asm("fma.rn.f32x2 %0, %1, %2, %0;" : "+l"(acc[2 * s])     : "l"(x0), "l"(w2));
                asm("fma.rn.f32x2 %0, %1, %2, %0;" : "+l"(acc[2 * s + 1]) : "l"(x1), "l"(w2));
            }
        }
        __syncthreads();
    }

    int r0 = row_base + tid, r1 = row_base + 256 + tid;
#pragma unroll
    for (int s = 0; s < SUB1; s++) {
        float lo, hi;
        asm("mov.b64 {%0,%1}, %2;" : "=f"(lo), "=f"(hi) : "l"(acc[2 * s]));
        if (r0 < T) out[(size_t)r0 * 32 + 2 * s + ch] = lo + hi;
        asm("mov.b64 {%0,%1}, %2;" : "=f"(lo), "=f"(hi) : "l"(acc[2 * s + 1]));
        if (r1 < T) out[(size_t)r1 * 32 + 2 * s + ch] = lo + hi;
    }
}

// ---------------- sliding-window depthwise conv, f32x2-packed ----------------
// acc2[r] += sum_d sig2[(base+r-d)*PITCH] * w2[d]   (both lanes in parallel)
template <int NT, int PITCH>
__device__ __forceinline__ void conv_slide2(unsigned long long acc[8],
                                            const float2* __restrict__ sig,
                                            const float2* __restrict__ w, int base) {
    unsigned long long y[8];
#pragma unroll
    for (int j = 0; j < 8; j++) y[j] = *(const unsigned long long*)(sig + (base + j) * PITCH);
#pragma unroll 1
    for (int d0 = 0; d0 < NT; d0 += 8) {
#pragma unroll
        for (int dd = 0; dd < 8; dd++) {
            unsigned long long w2 = *(const unsigned long long*)(w + d0 + dd);
#pragma unroll
            for (int r = 0; r < 8; r++)
                asm("fma.rn.f32x2 %0, %1, %2, %0;" : "+l"(acc[r]) : "l"(y[(r - dd) & 7]), "l"(w2));
            y[(7 - dd) & 7] = *(const unsigned long long*)(sig + (base - (d0 + dd) - 1) * PITCH);
        }
    }
}

// scalar variant (obs high taps)
template <int NT, int PITCH>
__device__ __forceinline__ void conv_slide_s(float acc[8], const float* __restrict__ sig,
                                             const float* __restrict__ w, int base) {
    float y[8];
#pragma unroll
    for (int j = 0; j < 8; j++) y[j] = sig[(base + j) * PITCH];
#pragma unroll 1
    for (int d0 = 0; d0 < NT; d0 += 8) {
#pragma unroll
        for (int dd = 0; dd < 8; dd++) {
            float wv = w[d0 + dd];
#pragma unroll
            for (int r = 0; r < 8; r++)
                acc[r] = fmaf(y[(r - dd) & 7], wv, acc[r]);
            y[(7 - dd) & 7] = sig[(base - (d0 + dd) - 1) * PITCH];
        }
    }
}

// out[t,s] = exp( conv_ei + conv_hist + conv_obs + Theta[s] )
// block: 128 t, 256 threads -> s = tid&15 (15 used), 16 t-runs of 8 t each.
__global__ __launch_bounds__(256, 2) void conv_kernel(const float* __restrict__ Z_obs,
                                                      const float* __restrict__ Z_hid,
                                                      const float* __restrict__ Theta,
                                                      float* __restrict__ out0,
                                                      float* __restrict__ out1,
                                                      int T) {
    extern __shared__ float sm[];
    float2* sei = (float2*)sm;             // [232][17]  {syn_e, syn_i}, origin t0-104
    float2* hz  = sei + 232 * 17;          // [232][17]  {Z_hid[u], Z_obs[u+101]}, origin t0-104
    float*  zo  = (float*)(hz + 232 * 17); // [232]      Z_obs, origin t0-108
    float2* wei = (float2*)(zo + 232);     // [15][105]  {ke, ki}
    float2* whz = wei + SUB1 * 105;        // [15][105]  {kh, ko_lo}
    float*  koh = (float*)(whz + SUB1 * 105); // [15*105] ko_hi
    const int tid = threadIdx.x;
    const int t0 = blockIdx.x * 128;

    for (int li = tid; li < 232 * 16; li += 256) {
        int lt = li >> 4, s = li & 15;
        int t = t0 - 104 + lt;
        float2 v = make_float2(0.f, 0.f);
        if (s < SUB1 && t >= 0 && t < T) v = *(const float2*)(g_syn + (size_t)t * 32 + 2 * s);
        sei[lt * 17 + s] = v;
        float zh = (s < SUB1 && t >= 0 && t < T) ? Z_hid[(size_t)t * SUB1 + s] : 0.f;
        int uz = t + 101;
        float zb = (uz >= 0 && uz < T) ? Z_obs[uz] : 0.f;
        hz[lt * 17 + s] = make_float2(zh, zb);
    }
    for (int li = tid; li < 232; li += 256) {
        int t = t0 - 108 + li;
        zo[li] = (t >= 0 && t < T) ? Z_obs[t] : 0.f;
    }
    for (int li = tid; li < SUB1 * 105; li += 256) {
        wei[li] = g_wei[li];
        whz[li] = g_whz[li];
        koh[li] = g_kohi[li];
    }
    __syncthreads();

    const int s = tid & 15;
    const int trun = tid >> 4;
    if (s >= SUB1) return;   // no barriers after this point

    unsigned long long acc2[8];
#pragma unroll
    for (int r = 0; r < 8; r++) acc2[r] = 0ull;
    float accs[8];
    float th = __ldg(Theta + s);
#pragma unroll
    for (int r = 0; r < 8; r++) accs[r] = th;

    // e+i packed:   sum_d {syn_e,syn_i}[t-d]   * {ke,ki}[d]
    conv_slide2<104, 17>(acc2, sei + s, wei + s * 105, 104 + trun * 8);
    // hist+obs_lo:  sum_d {Z_hid[t-1-d], Z_obs[t+100-d]} * {kh[d], ko[d]}
    conv_slide2<104, 17>(acc2, hz + s, whz + s * 105, 103 + trun * 8);
    // obs_hi:       sum_d Z_obs[t-4-d] * ko[104+d]
    conv_slide_s<104, 1>(accs, zo, koh + s * 105, 104 + trun * 8);

    const int tb = t0 + trun * 8;
#pragma unroll
    for (int r = 0; r < 8; r++) {
        int t = tb + r;
        if (t < T) {
            float lo, hi;
            asm("mov.b64 {%0,%1}, %2;" : "=f"(lo), "=f"(hi) : "l"(acc2[r]));
            float v = expf(lo + hi + accs[r]);
            out0[(size_t)t * SUB1 + s] = v;
            out1[(size_t)t * SUB1 + s] = v;
        }
    }
}

extern "C" void kernel_launch(void* const* d_in, const int* in_sizes, int n_in,
                              void* d_out, int out_size) {
    const float* S_e    = (const float*)d_in[0];
    const float* S_i    = (const float*)d_in[1];
    const float* Z_obs  = (const float*)d_in[2];
    const float* Z_hid  = (const float*)d_in[3];
    const float* C_e    = (const float*)d_in[4];
    const float* C_i    = (const float*)d_in[5];
    const float* W_syn  = (const float*)d_in[6];
    const float* W_hist = (const float*)d_in[7];
    const float* W_obs  = (const float*)d_in[8];
    const float* Theta  = (const float*)d_in[9];
    const int T = in_sizes[2];          // Z_obs element count

    float* out0 = (float*)d_out;
    float* out1 = (out_size >= 2 * T * SUB1) ? out0 + (size_t)T * SUB1 : out0;

    const int smem_mm_e = (512 * 34 + 2 * SUB1 * 16) * (int)sizeof(float);  // 71,552
    const int smem_mm_i = (512 * 42 + 2 * SUB1 * 20) * (int)sizeof(float);  // 88,416
    const int smem_conv = (2 * 232 * 17 * 2 + 232 + 2 * SUB1 * 105 * 2 + SUB1 * 105) * (int)sizeof(float); // 95,532

    cudaFuncSetAttribute(matmul_kernel<800, 32>, cudaFuncAttributeMaxDynamicSharedMemorySize, smem_mm_e);
    cudaFuncSetAttribute(matmul_kernel<200, 40>, cudaFuncAttributeMaxDynamicSharedMemorySize, smem_mm_i);
    cudaFuncSetAttribute(conv_kernel,            cudaFuncAttributeMaxDynamicSharedMemorySize, smem_conv);

    float* syn_ptr;
    cudaGetSymbolAddress((void**)&syn_ptr, g_syn);

    prep_kernel<<<(SUB1 * 105 + 255) / 256, 256>>>(W_syn, W_hist, W_obs);

    int mm_blocks = (T + 511) / 512;
    matmul_kernel<800, 32><<<mm_blocks, 256, smem_mm_e>>>(S_e, C_e, syn_ptr, T, 0);
    matmul_kernel<200, 40><<<mm_blocks, 256, smem_mm_i>>>(S_i, C_i, syn_ptr, T, 1);

    int conv_blocks = (T + 127) / 128;
    conv_kernel<<<conv_blocks, 256, smem_conv>>>(Z_obs, Z_hid, Theta, out0, out1, T);
}

// round 7
// speedup vs baseline: 2.1721x; 1.5308x over previous
#include <cuda_runtime.h>
#include <math.h>

#define SUB1 15
#define T_MAX 120000

// ---------------- scratch (device globals — no allocs allowed) ----------------
__device__ float  g_syn[T_MAX * 32];      // interleaved {e,i} per (t,s): [t][s][2], s-pitch 32
__device__ float2 g_wei[SUB1 * 105];      // {ke[d], ki[d]}
__device__ float2 g_whz[SUB1 * 105];      // {kh[d], ko[d]}        (obs taps 0..103)
__device__ float  g_kohi[SUB1 * 105];     // ko[104+d]             (obs taps 104..207)

// ---------------- basis functions (fp32, MUFU-fast; boundary flips hit ~0-valued taps) ----
__device__ __forceinline__ float cos_basis_f(int b, int d) {
    const float PI_F = 3.14159265358979f;
    float raw = 5.0f * logf((float)d + 1.0f + 1e-8f);
    float phi = 1.5707963267948966f * (float)b;
    if (raw < phi - PI_F || raw > phi + PI_F) return 0.f;
    return 0.5f * cosf(raw - phi) + 0.5f;
}

__device__ __forceinline__ float obs_basis_f(int b, int x) {
    const float PI_F = 3.14159265358979f;
    float phi;
    if (b == 0) {
        phi = 0.f;
    } else if (b & 1) {           // positive-side basis (x >= 0)
        if (x < 0) return 0.f;
        phi = 1.5707963267948966f * (float)((b + 1) >> 1);
    } else {                      // negative-side basis (x <= 0)
        if (x > 0) return 0.f;
        phi = 1.5707963267948966f * (float)(b >> 1);
    }
    float r = 5.0f * logf(fabsf((float)x) + 1.0f + 1e-8f);
    if (r < phi - PI_F || r > phi + PI_F) return 0.f;
    return 0.5f * cosf(r - phi) + 0.5f;
}

// ---------------- kernel precompute (tiny, fp32) ----------------
__global__ void prep_kernel(const float* __restrict__ W_syn,
                            const float* __restrict__ W_hist,
                            const float* __restrict__ W_obs) {
    int idx = blockIdx.x * blockDim.x + threadIdx.x;
    if (idx >= SUB1 * 105) return;
    int s = idx / 105, d = idx % 105;
    float ke = 0.f, ki = 0.f, kh = 0.f, ko = 0.f, ko2 = 0.f;
    if (d < 100) {
        for (int b = 0; b < 13; b++) {
            float bf = cos_basis_f(b, d);
            ke = fmaf(W_syn[(s * 13 + b) * 2 + 0], bf, ke);
            ki = fmaf(W_syn[(s * 13 + b) * 2 + 1], bf, ki);
            kh = fmaf(W_hist[s * 13 + b], bf, kh);
        }
    }
    if (d < 104) {  // obs tap j = d, x = j - 100
        for (int b = 0; b < 25; b++)
            ko = fmaf(W_obs[s * 25 + b], obs_basis_f(b, d - 100), ko);
    }
    if (d <= 96) {  // obs tap j = 104 + d, x = d + 4  (j <= 200)
        for (int b = 0; b < 25; b++)
            ko2 = fmaf(W_obs[s * 25 + b], obs_basis_f(b, d + 4), ko2);
    }
    g_wei[idx]  = make_float2(ke, ki);
    g_whz[idx]  = make_float2(kh, ko);
    g_kohi[idx] = ko2;
}

// ---------------- matmul: syn[t,s] = sum_k S[t,k] * C[s+1,k] ----------------
// k-pair packing into f32x2. 256 threads, 2 rows/thread (tid, tid+256), 512 rows/block.
template <int K, int KC>
__global__ __launch_bounds__(256, 2) void matmul_kernel(const float* __restrict__ S,
                                                        const float* __restrict__ C,
                                                        float* __restrict__ out,
                                                        int T, int ch) {
    extern __shared__ float sm[];
    const int PITCH = KC + 2;                    // even -> float2-aligned rows
    float* tile = sm;                            // [512][PITCH]
    float2* wbuf = (float2*)(sm + 512 * PITCH);  // [15][KC/2]
    const int tid = threadIdx.x;
    const int row_base = blockIdx.x * 512;

    unsigned long long acc[2 * SUB1];
#pragma unroll
    for (int i = 0; i < 2 * SUB1; i++) acc[i] = 0ull;

    for (int k0 = 0; k0 < K; k0 += KC) {
        for (int li = tid; li < SUB1 * (KC / 2); li += 256) {
            int s = li / (KC / 2), q = li % (KC / 2);
            wbuf[li] = *(const float2*)(C + (size_t)(s + 1) * K + k0 + 2 * q);
        }
#pragma unroll
        for (int it = 0; it < (512 * KC / 4) / 256; it++) {
            int li = it * 256 + tid;
            int r = li / (KC / 4), q = li % (KC / 4);
            int row = row_base + r;
            float4 v = make_float4(0.f, 0.f, 0.f, 0.f);
            if (row < T) v = *(const float4*)(S + (size_t)row * K + k0 + 4 * q);
            float* dst = tile + r * PITCH + 4 * q;
            *(float2*)(dst)     = make_float2(v.x, v.y);
            *(float2*)(dst + 2) = make_float2(v.z, v.w);
        }
        __syncthreads();
#pragma unroll
        for (int j = 0; j < KC / 2; j++) {
            unsigned long long x0 = *(const unsigned long long*)(tile + tid * PITCH + 2 * j);
            unsigned long long x1 = *(const unsigned long long*)(tile + (tid + 256) * PITCH + 2 * j);
#pragma unroll
            for (int s = 0; s < SUB1; s++) {
                unsigned long long w2 = *(const unsigned long long*)(wbuf + s * (KC / 2) + j);
                asm("fma.rn.f32x2 %0, %1, %2, %0;" : "+l"(acc[2 * s])     : "l"(x0), "l"(w2));
                asm("fma.rn.f32x2 %0, %1, %2, %0;" : "+l"(acc[2 * s + 1]) : "l"(x1), "l"(w2));
            }
        }
        __syncthreads();
    }

    int r0 = row_base + tid, r1 = row_base + 256 + tid;
#pragma unroll
    for (int s = 0; s < SUB1; s++) {
        float lo, hi;
        asm("mov.b64 {%0,%1}, %2;" : "=f"(lo), "=f"(hi) : "l"(acc[2 * s]));
        if (r0 < T) out[(size_t)r0 * 32 + 2 * s + ch] = lo + hi;
        asm("mov.b64 {%0,%1}, %2;" : "=f"(lo), "=f"(hi) : "l"(acc[2 * s + 1]));
        if (r1 < T) out[(size_t)r1 * 32 + 2 * s + ch] = lo + hi;
    }
}

// ---------------- fused sliding-window conv: 3 interleaved chains ----------------
// acc2[r] += sei[a+r-d]*wei[d] + hz[b+r-d]*whz[d]   (both f32x2, one accumulator)
// accs[r] += zo[c+r-d]*koh[d]
// Load->use distance ~27 instrs covers the 29-cyc LDS latency.
__device__ __forceinline__ void conv_fused(unsigned long long acc2[8], float accs[8],
                                           const float2* __restrict__ sei,
                                           const float2* __restrict__ wei,
                                           const float2* __restrict__ hz,
                                           const float2* __restrict__ whz,
                                           const float* __restrict__ zo,
                                           const float* __restrict__ koh,
                                           int base_a, int base_b, int base_c) {
    unsigned long long ya[8], yb[8];
    float yc[8];
#pragma unroll
    for (int j = 0; j < 8; j++) {
        ya[j] = *(const unsigned long long*)(sei + (base_a + j) * 17);
        yb[j] = *(const unsigned long long*)(hz + (base_b + j) * 17);
        yc[j] = zo[base_c + j];
    }
#pragma unroll 1
    for (int d0 = 0; d0 < 104; d0 += 8) {
#pragma unroll
        for (int dd = 0; dd < 8; dd++) {
            unsigned long long wa = *(const unsigned long long*)(wei + d0 + dd);
            unsigned long long wb = *(const unsigned long long*)(whz + d0 + dd);
            float wc = koh[d0 + dd];
#pragma unroll
            for (int r = 0; r < 8; r++)
                asm("fma.rn.f32x2 %0, %1, %2, %0;" : "+l"(acc2[r]) : "l"(ya[(r - dd) & 7]), "l"(wa));
#pragma unroll
            for (int r = 0; r < 8; r++)
                asm("fma.rn.f32x2 %0, %1, %2, %0;" : "+l"(acc2[r]) : "l"(yb[(r - dd) & 7]), "l"(wb));
#pragma unroll
            for (int r = 0; r < 8; r++)
                accs[r] = fmaf(yc[(r - dd) & 7], wc, accs[r]);
            ya[(7 - dd) & 7] = *(const unsigned long long*)(sei + (base_a - (d0 + dd) - 1) * 17);
            yb[(7 - dd) & 7] = *(const unsigned long long*)(hz + (base_b - (d0 + dd) - 1) * 17);
            yc[(7 - dd) & 7] = zo[base_c - (d0 + dd) - 1];
        }
    }
}

// out[t,s] = exp( conv_ei + conv_hist + conv_obs + Theta[s] )
__global__ __launch_bounds__(256, 2) void conv_kernel(const float* __restrict__ Z_obs,
                                                      const float* __restrict__ Z_hid,
                                                      const float* __restrict__ Theta,
                                                      float* __restrict__ out0,
                                                      float* __restrict__ out1,
                                                      int T) {
    extern __shared__ float sm[];
    float2* sei = (float2*)sm;             // [232][17]  {syn_e, syn_i}, origin t0-104
    float2* hz  = sei + 232 * 17;          // [232][17]  {Z_hid[u], Z_obs[u+101]}, origin t0-104
    float*  zo  = (float*)(hz + 232 * 17); // [232]      Z_obs, origin t0-108
    float2* wei = (float2*)(zo + 232);     // [15][105]  {ke, ki}
    float2* whz = wei + SUB1 * 105;        // [15][105]  {kh, ko_lo}
    float*  koh = (float*)(whz + SUB1 * 105); // [15*105] ko_hi
    const int tid = threadIdx.x;
    const int t0 = blockIdx.x * 128;

    for (int li = tid; li < 232 * 16; li += 256) {
        int lt = li >> 4, s = li & 15;
        int t = t0 - 104 + lt;
        float2 v = make_float2(0.f, 0.f);
        if (s < SUB1 && t >= 0 && t < T) v = *(const float2*)(g_syn + (size_t)t * 32 + 2 * s);
        sei[lt * 17 + s] = v;
        float zh = (s < SUB1 && t >= 0 && t < T) ? Z_hid[(size_t)t * SUB1 + s] : 0.f;
        int uz = t + 101;
        float zb = (uz >= 0 && uz < T) ? Z_obs[uz] : 0.f;
        hz[lt * 17 + s] = make_float2(zh, zb);
    }
    for (int li = tid; li < 232; li += 256) {
        int t = t0 - 108 + li;
        zo[li] = (t >= 0 && t < T) ? Z_obs[t] : 0.f;
    }
    for (int li = tid; li < SUB1 * 105; li += 256) {
        wei[li] = g_wei[li];
        whz[li] = g_whz[li];
        koh[li] = g_kohi[li];
    }
    __syncthreads();

    const int s = tid & 15;
    const int trun = tid >> 4;
    if (s >= SUB1) return;   // no barriers after this point

    unsigned long long acc2[8];
#pragma unroll
    for (int r = 0; r < 8; r++) acc2[r] = 0ull;
    float accs[8];
    float th = __ldg(Theta + s);
#pragma unroll
    for (int r = 0; r < 8; r++) accs[r] = th;

    conv_fused(acc2, accs,
               sei + s, wei + s * 105,
               hz + s, whz + s * 105,
               zo, koh + s * 105,
               104 + trun * 8,    // ei:   sum_d {syn_e,syn_i}[t-d] * {ke,ki}[d]
               103 + trun * 8,    // hz:   sum_d {Z_hid[t-1-d], Z_obs[t+100-d]} * {kh,ko}[d]
               104 + trun * 8);   // obs:  sum_d Z_obs[t-4-d] * ko[104+d]

    const int tb = t0 + trun * 8;
#pragma unroll
    for (int r = 0; r < 8; r++) {
        int t = tb + r;
        if (t < T) {
            float lo, hi;
            asm("mov.b64 {%0,%1}, %2;" : "=f"(lo), "=f"(hi) : "l"(acc2[r]));
            float v = expf(lo + hi + accs[r]);
            out0[(size_t)t * SUB1 + s] = v;
            out1[(size_t)t * SUB1 + s] = v;
        }
    }
}

extern "C" void kernel_launch(void* const* d_in, const int* in_sizes, int n_in,
                              void* d_out, int out_size) {
    const float* S_e    = (const float*)d_in[0];
    const float* S_i    = (const float*)d_in[1];
    const float* Z_obs  = (const float*)d_in[2];
    const float* Z_hid  = (const float*)d_in[3];
    const float* C_e    = (const float*)d_in[4];
    const float* C_i    = (const float*)d_in[5];
    const float* W_syn  = (const float*)d_in[6];
    const float* W_hist = (const float*)d_in[7];
    const float* W_obs  = (const float*)d_in[8];
    const float* Theta  = (const float*)d_in[9];
    const int T = in_sizes[2];          // Z_obs element count

    float* out0 = (float*)d_out;
    float* out1 = (out_size >= 2 * T * SUB1) ? out0 + (size_t)T * SUB1 : out0;

    const int smem_mm_e = (512 * 34 + 2 * SUB1 * 16) * (int)sizeof(float);  // 71,552
    const int smem_mm_i = (512 * 42 + 2 * SUB1 * 20) * (int)sizeof(float);  // 88,416
    const int smem_conv = (2 * 232 * 17 * 2 + 232 + 2 * SUB1 * 105 * 2 + SUB1 * 105) * (int)sizeof(float); // 95,532

    cudaFuncSetAttribute(matmul_kernel<800, 32>, cudaFuncAttributeMaxDynamicSharedMemorySize, smem_mm_e);
    cudaFuncSetAttribute(matmul_kernel<200, 40>, cudaFuncAttributeMaxDynamicSharedMemorySize, smem_mm_i);
    cudaFuncSetAttribute(conv_kernel,            cudaFuncAttributeMaxDynamicSharedMemorySize, smem_conv);

    float* syn_ptr;
    cudaGetSymbolAddress((void**)&syn_ptr, g_syn);

    prep_kernel<<<(SUB1 * 105 + 255) / 256, 256>>>(W_syn, W_hist, W_obs);

    int mm_blocks = (T + 511) / 512;
    matmul_kernel<800, 32><<<mm_blocks, 256, smem_mm_e>>>(S_e, C_e, syn_ptr, T, 0);
    matmul_kernel<200, 40><<<mm_blocks, 256, smem_mm_i>>>(S_i, C_i, syn_ptr, T, 1);

    int conv_blocks = (T + 127) / 128;
    conv_kernel<<<conv_blocks, 256, smem_conv>>>(Z_obs, Z_hid, Theta, out0, out1, T);
}